// round 12
// baseline (speedup 1.0000x reference)
#include <cuda_runtime.h>
#include <cstdint>

#define PACT 484      // 22*22 active pixels
#define NB   32

// Scratch (static device allocations - allowed)
__device__ float    g_qkva [(size_t)NB * 768 * PACT];    // qp | k | v at active pixels
__device__ float    g_oscr [(size_t)NB * 4 * 100 * 1024];// o patches [n][h][s][l(16)][d(64)]
__device__ float    g_pout [(size_t)NB * 256 * PACT];    // proj output at active pixels
__device__ unsigned g_wfrag1[48 * 32 * 128];             // [w_q;w_kv] tf32 A-fragments
__device__ unsigned g_wfrag2[16 * 32 * 128];             // w_proj tf32 A-fragments
__device__ unsigned g_qpack[(size_t)NB * 32 * 512 * 8];  // gathered q, tf32 B-fragment layout
__device__ float    g_bias768[768];

__device__ __forceinline__ unsigned f2tf(float f) {
    unsigned r; asm("cvt.rna.tf32.f32 %0, %1;" : "=r"(r) : "f"(f)); return r;
}

__device__ __forceinline__ void mma_tf32(float* d, const unsigned* a, unsigned b0, unsigned b1) {
    asm("mma.sync.aligned.m16n8k8.row.col.f32.tf32.tf32.f32 "
        "{%0,%1,%2,%3},{%4,%5,%6,%7},{%8,%9},{%0,%1,%2,%3};\n"
        : "+f"(d[0]), "+f"(d[1]), "+f"(d[2]), "+f"(d[3])
        : "r"(a[0]), "r"(a[1]), "r"(a[2]), "r"(a[3]), "r"(b0), "r"(b1));
}

__device__ __forceinline__ void cp_async16(void* smem_dst, const void* gmem_src) {
    unsigned dst = (unsigned)__cvta_generic_to_shared(smem_dst);
    asm volatile("cp.async.cg.shared.global [%0], [%1], 16;\n"
                 :: "r"(dst), "l"(gmem_src));
}
__device__ __forceinline__ void cp_commit() {
    asm volatile("cp.async.commit_group;\n");
}
__device__ __forceinline__ void cp_wait2() {
    asm volatile("cp.async.wait_group 2;\n");
}

// ---------------------------------------------------------------------------
// Prep: weights -> mma A-fragment-native tf32 layout, concat biases.
// ---------------------------------------------------------------------------
__global__ __launch_bounds__(256) void prep_kernel(const float* __restrict__ w_q,
                                                   const float* __restrict__ b_q,
                                                   const float* __restrict__ w_kv,
                                                   const float* __restrict__ b_kv,
                                                   const float* __restrict__ w_proj) {
    int t = blockIdx.x * 256 + threadIdx.x;
    if (t < 49152) {                      // 48 mt * 32 ks * 32 lanes
        int lane = t & 31, ks = (t >> 5) & 31, mtg = t >> 10;
        int gid = lane >> 2, ctid = lane & 3;
        int r0 = mtg * 16 + gid, r1 = r0 + 8;
        int k0 = ks * 8 + ctid, k1 = k0 + 4;
        const float* W; int rb;
        if (r0 < 256) { W = w_q; rb = 0; } else { W = w_kv; rb = 256; }
        uint4 v = make_uint4(f2tf(W[(size_t)(r0 - rb) * 256 + k0]),
                             f2tf(W[(size_t)(r1 - rb) * 256 + k0]),
                             f2tf(W[(size_t)(r0 - rb) * 256 + k1]),
                             f2tf(W[(size_t)(r1 - rb) * 256 + k1]));
        ((uint4*)g_wfrag1)[t] = v;
    } else if (t < 49152 + 16384) {       // 16 mt * 32 ks * 32 lanes
        int u = t - 49152;
        int lane = u & 31, ks = (u >> 5) & 31, mtg = u >> 10;
        int gid = lane >> 2, ctid = lane & 3;
        int r0 = mtg * 16 + gid, r1 = r0 + 8;
        int k0 = ks * 8 + ctid, k1 = k0 + 4;
        uint4 v = make_uint4(f2tf(w_proj[(size_t)r0 * 256 + k0]),
                             f2tf(w_proj[(size_t)r1 * 256 + k0]),
                             f2tf(w_proj[(size_t)r0 * 256 + k1]),
                             f2tf(w_proj[(size_t)r1 * 256 + k1]));
        ((uint4*)g_wfrag2)[u] = v;
    } else if (t < 49152 + 16384 + 768) {
        int o = t - 49152 - 16384;
        g_bias768[o] = (o < 256) ? b_q[o] : b_kv[o - 256];
    }
}

// ---------------------------------------------------------------------------
// Pack: gather q at active pixels -> tf32 B-fragment-native layout.
// ---------------------------------------------------------------------------
__global__ __launch_bounds__(256) void pack_q(const float* __restrict__ q) {
    const int p  = blockIdx.x * 256 + threadIdx.x;   // 0..511
    const int kg = blockIdx.y;                       // 0..31
    const int n  = blockIdx.z;
    const float* qn = q + (size_t)n * 256 * 4096;
    unsigned o[8];
    if (p < PACT) {
        int m = p / 22, m2 = p - m * 22;
        size_t base = (size_t)(kg * 8) * 4096 + m * 192 + m2 * 3;
#pragma unroll
        for (int kk = 0; kk < 8; kk++)
            o[(kk & 3) * 2 + (kk >> 2)] = f2tf(qn[base + (size_t)kk * 4096]);
    } else {
#pragma unroll
        for (int i = 0; i < 8; i++) o[i] = 0u;
    }
    uint4* dst = (uint4*)(g_qpack + ((size_t)(n * 32 + kg) * 512 + p) * 8);
    dst[0] = make_uint4(o[0], o[1], o[2], o[3]);
    dst[1] = make_uint4(o[4], o[5], o[6], o[7]);
}

// ---------------------------------------------------------------------------
// TF32 GEMM1: per n, OUT(768,484) = [w_q;w_kv] @ gather(q) + bias
// B staged via 4-stage cp.async ring; A register-prefetched. float2 epilogue.
// ---------------------------------------------------------------------------
__global__ __launch_bounds__(256, 2) void gemm_qkv_tc() {
    __shared__ unsigned Bs[4][2][1024];   // 32 KB ring
    const int n = blockIdx.z, o0 = blockIdx.y * 128, p0 = blockIdx.x * 128;
    const int tid = threadIdx.x, lane = tid & 31, wid = tid >> 5;
    const int warp_m = wid >> 1, warp_n = wid & 1;
    const int gid = lane >> 2, ctid = lane & 3;

    float acc[2][8][4] = {};

    const uint4* src = (const uint4*)(g_qpack + ((size_t)(n * 32) * 512 + p0) * 8);
    auto issue_stage = [&](int s) {
#pragma unroll
        for (int ks = 0; ks < 2; ks++) {
            int kg = s * 2 + ks;
            cp_async16(&((uint4*)Bs[s & 3][ks])[tid], &src[(size_t)kg * 1024 + tid]);
        }
    };
    issue_stage(0); cp_commit();
    issue_stage(1); cp_commit();
    issue_stage(2); cp_commit();

    const int mtg0 = (o0 >> 4) + warp_m * 2;
    uint4 a_next[2];
#pragma unroll
    for (int mt = 0; mt < 2; mt++)
        a_next[mt] = ((const uint4*)g_wfrag1)[((mtg0 + mt) * 32 + 0) * 32 + lane];

    for (int iter = 0; iter < 16; iter++) {
        cp_wait2();
        __syncthreads();
        if (iter + 3 < 16) issue_stage(iter + 3);
        cp_commit();
        const int buf = iter & 3;
#pragma unroll
        for (int ks = 0; ks < 2; ks++) {
            int ksg = iter * 2 + ks;
            uint4 a_cur[2]; a_cur[0] = a_next[0]; a_cur[1] = a_next[1];
            if (ksg + 1 < 32) {
#pragma unroll
                for (int mt = 0; mt < 2; mt++)
                    a_next[mt] = ((const uint4*)g_wfrag1)[((mtg0 + mt) * 32 + ksg + 1) * 32 + lane];
            }
            unsigned a0[4] = {a_cur[0].x, a_cur[0].y, a_cur[0].z, a_cur[0].w};
            unsigned a1[4] = {a_cur[1].x, a_cur[1].y, a_cur[1].z, a_cur[1].w};
#pragma unroll
            for (int nt = 0; nt < 8; nt++) {
                const unsigned* bp = &Bs[buf][ks][warp_n * 512 + nt * 64 + lane * 2];
                unsigned b0 = bp[0], b1 = bp[1];
                mma_tf32(acc[0][nt], a0, b0, b1);
                mma_tf32(acc[1][nt], a1, b0, b1);
            }
        }
    }

    float* outb = g_qkva + (size_t)n * 768 * PACT;
#pragma unroll
    for (int mt = 0; mt < 2; mt++) {
        int row0 = o0 + warp_m * 32 + mt * 16 + gid;
#pragma unroll
        for (int half = 0; half < 2; half++) {
            int o = row0 + half * 8;
            float bv = g_bias768[o];
#pragma unroll
            for (int nt = 0; nt < 8; nt++) {
                int col = p0 + warp_n * 64 + nt * 8 + ctid * 2;   // always even
                if (col < PACT)
                    *(float2*)&outb[(size_t)o * PACT + col] =
                        make_float2(acc[mt][nt][half * 2 + 0] + bv,
                                    acc[mt][nt][half * 2 + 1] + bv);
            }
        }
    }
}

// ---------------------------------------------------------------------------
// TF32 GEMM2 + fused fold: per n, POUT(256,484) = w_proj @ fold(o) + b_proj
// B[k][p] computed on the fly from g_oscr (<=4 combo segments, same add
// order as the old fold kernel -> bit-identical). Register software-pipeline.
// ---------------------------------------------------------------------------
__global__ __launch_bounds__(256, 2) void gemm_proj_tc(const float* __restrict__ b_proj) {
    __shared__ unsigned Bs[2][2][1024];
    const int n = blockIdx.z, o0 = blockIdx.y * 128, p0 = blockIdx.x * 128;
    const int tid = threadIdx.x, lane = tid & 31, wid = tid >> 5;
    const int warp_m = wid >> 1, warp_n = wid & 1;
    const int gid = lane >> 2, ctid = lane & 3;

    float acc[2][8][4] = {};

    const int pl = tid & 127, kh = tid >> 7;
    const int pg = p0 + pl;

    // fold combos for pixel pg: offsets into per-(n,h) o block (floats)
    int coff[4]; int ncombo = 0;
    if (pg < PACT) {
        int m = pg / 22, m2 = pg - (pg / 22) * 22;
        int a_off[2]; int na = 0;
#pragma unroll
        for (int t = 0; t < 2; t++) {
            int ja = (m & 1) + 2 * t;
            int d = m - ja;
            if (d >= 0 && d <= 18) a_off[na++] = (d >> 1) * 10240 + ja * 256;
        }
        int b_off[2]; int nbv = 0;
#pragma unroll
        for (int t = 0; t < 2; t++) {
            int jb = (m2 & 1) + 2 * t;
            int d = m2 - jb;
            if (d >= 0 && d <= 18) b_off[nbv++] = (d >> 1) * 1024 + jb * 64;
        }
        for (int a = 0; a < na; a++)
            for (int b = 0; b < nbv; b++)
                coff[ncombo++] = a_off[a] + b_off[b];
    }
    const float* base_n = g_oscr + (size_t)(n * 4) * 102400;

    float rvals[8];
    auto load_regs = [&](int iter) {
        int k0 = iter * 16 + kh * 8;
        int hh = k0 >> 6, d0 = k0 & 63;
        float4 aa = make_float4(0.f, 0.f, 0.f, 0.f);
        float4 bb = make_float4(0.f, 0.f, 0.f, 0.f);
        const float* bh = base_n + (size_t)hh * 102400 + d0;
        for (int c = 0; c < ncombo; c++) {
            const float4* s = (const float4*)(bh + coff[c]);
            float4 x = s[0], y = s[1];
            aa.x += x.x; aa.y += x.y; aa.z += x.z; aa.w += x.w;
            bb.x += y.x; bb.y += y.y; bb.z += y.z; bb.w += y.w;
        }
        rvals[0] = aa.x; rvals[1] = aa.y; rvals[2] = aa.z; rvals[3] = aa.w;
        rvals[4] = bb.x; rvals[5] = bb.y; rvals[6] = bb.z; rvals[7] = bb.w;
    };
    auto store_stage = [&](int iter) {
        int buf = iter & 1;
        unsigned o[8];
#pragma unroll
        for (int kk = 0; kk < 8; kk++)
            o[(kk & 3) * 2 + (kk >> 2)] = f2tf(rvals[kk]);
        uint4* dst = (uint4*)&Bs[buf][kh][pl * 8];
        dst[0] = make_uint4(o[0], o[1], o[2], o[3]);
        dst[1] = make_uint4(o[4], o[5], o[6], o[7]);
    };
    load_regs(0);
    store_stage(0);
    load_regs(1);
    __syncthreads();

    const int mtg0 = (o0 >> 4) + warp_m * 2;
    uint4 a_next[2];
#pragma unroll
    for (int mt = 0; mt < 2; mt++)
        a_next[mt] = ((const uint4*)g_wfrag2)[((mtg0 + mt) * 32 + 0) * 32 + lane];

    for (int iter = 0; iter < 16; iter++) {
        const int buf = iter & 1;
#pragma unroll
        for (int ks = 0; ks < 2; ks++) {
            int ksg = iter * 2 + ks;
            uint4 a_cur[2]; a_cur[0] = a_next[0]; a_cur[1] = a_next[1];
            if (ksg + 1 < 32) {
#pragma unroll
                for (int mt = 0; mt < 2; mt++)
                    a_next[mt] = ((const uint4*)g_wfrag2)[((mtg0 + mt) * 32 + ksg + 1) * 32 + lane];
            }
            unsigned a0[4] = {a_cur[0].x, a_cur[0].y, a_cur[0].z, a_cur[0].w};
            unsigned a1[4] = {a_cur[1].x, a_cur[1].y, a_cur[1].z, a_cur[1].w};
#pragma unroll
            for (int nt = 0; nt < 8; nt++) {
                const unsigned* bp = &Bs[buf][ks][warp_n * 512 + nt * 64 + lane * 2];
                unsigned b0 = bp[0], b1 = bp[1];
                mma_tf32(acc[0][nt], a0, b0, b1);
                mma_tf32(acc[1][nt], a1, b0, b1);
            }
        }
        if (iter + 1 < 16) store_stage(iter + 1);   // consumes rvals(iter+1)
        if (iter + 2 < 16) load_regs(iter + 2);     // refills rvals
        __syncthreads();
    }

    float* outb = g_pout + (size_t)n * 256 * PACT;
#pragma unroll
    for (int mt = 0; mt < 2; mt++) {
        int row0 = o0 + warp_m * 32 + mt * 16 + gid;
#pragma unroll
        for (int half = 0; half < 2; half++) {
            int o = row0 + half * 8;
            float bv = b_proj[o];
#pragma unroll
            for (int nt = 0; nt < 8; nt++) {
                int col = p0 + warp_n * 64 + nt * 8 + ctid * 2;   // always even
                if (col < PACT)
                    *(float2*)&outb[(size_t)o * PACT + col] =
                        make_float2(acc[mt][nt][half * 2 + 0] + bv,
                                    acc[mt][nt][half * 2 + 1] + bv);
            }
        }
    }
}

// ---------------------------------------------------------------------------
// Attention: block per (n, h, half-row). 5 patches s0..s0+4 in row i.
// Union: 4 image rows x 12 cols = 48 slots. Tiles [slot][d(64)+4pad].
// sc is OVERLAID on qs (qs dead after score phase; probs held in acc regs
// across a barrier) -> smem 38.25 KB -> 5 CTAs/SM.
// ---------------------------------------------------------------------------
__global__ __launch_bounds__(256, 5) void attn_kernel() {
    __shared__ float qs[48][68];
    __shared__ float ks[48][68];
    __shared__ float vs[48][68];
    float (*sc)[16][20] = (float(*)[16][20])&qs[0][0];   // overlay (6.4KB < 13KB)

    const int bx = blockIdx.x;         // 0..19
    const int i = bx >> 1;
    const int half = bx & 1;
    const int i2_0 = half * 5;
    const int s0 = i * 10 + i2_0;
    const int h = blockIdx.y;
    const int n = blockIdx.z;
    const int p0 = i * 44 + 2 * i2_0;

    const int tid = threadIdx.x;
    const int lane = tid & 31, wid = tid >> 5;
    const float* base = g_qkva + ((size_t)n * 768 + h * 64) * PACT + p0;

    // ---- staging: unit u = dg*48 + slot ----
    for (int u = tid; u < 768; u += 256) {
        const int dg = u / 48, slot = u - dg * 48;
        const int j = slot / 12, jc = slot - j * 12;
        const float* bq = base + (size_t)(dg * 4) * PACT + j * 22 + jc;
        const float* bk = bq + (size_t)256 * PACT;
        const float* bv = bq + (size_t)512 * PACT;
        float4 qv, kv, vv;
        qv.x = bq[0] * 0.125f;
        qv.y = bq[PACT] * 0.125f;
        qv.z = bq[2 * PACT] * 0.125f;
        qv.w = bq[3 * PACT] * 0.125f;
        kv.x = bk[0]; kv.y = bk[PACT]; kv.z = bk[2 * PACT]; kv.w = bk[3 * PACT];
        vv.x = bv[0]; vv.y = bv[PACT]; vv.z = bv[2 * PACT]; vv.w = bv[3 * PACT];
        *(float4*)&qs[slot][dg * 4] = qv;
        *(float4*)&ks[slot][dg * 4] = kv;
        *(float4*)&vs[slot][dg * 4] = vv;
    }
    __syncthreads();

    // ---- scores + softmax: warps 0..4 (patch = wid), lanes 0..15 ----
    const bool sact = (wid < 5 && lane < 16);
    float accr[4][4];
    const int pt = wid;
    const int txi = lane & 3;          // x = txi*4 + r
    const int tyi = lane >> 2;         // y = tyi*4 + c
    if (sact) {
        const int xs0 = txi * 12 + 2 * pt;
        const int ys0 = tyi * 12 + 2 * pt;
#pragma unroll
        for (int r = 0; r < 4; r++)
#pragma unroll
            for (int c = 0; c < 4; c++) accr[r][c] = 0.f;
#pragma unroll
        for (int dc = 0; dc < 16; dc++) {
            float4 kv[4];
#pragma unroll
            for (int c = 0; c < 4; c++) kv[c] = *(const float4*)&ks[ys0 + c][dc * 4];
#pragma unroll
            for (int r = 0; r < 4; r++) {
                float4 qv = *(const float4*)&qs[xs0 + r][dc * 4];
#pragma unroll
                for (int c = 0; c < 4; c++)
                    accr[r][c] += qv.x * kv[c].x + qv.y * kv[c].y
                                + qv.z * kv[c].z + qv.w * kv[c].w;
            }
        }
        // softmax in place (accr becomes normalized probs)
#pragma unroll
        for (int r = 0; r < 4; r++) {
            float m = fmaxf(fmaxf(accr[r][0], accr[r][1]), fmaxf(accr[r][2], accr[r][3]));
            m = fmaxf(m, __shfl_xor_sync(0x0000ffffu, m, 4));
            m = fmaxf(m, __shfl_xor_sync(0x0000ffffu, m, 8));
            float e0 = __expf(accr[r][0] - m), e1 = __expf(accr[r][1] - m);
            float e2 = __expf(accr[r][2] - m), e3 = __expf(accr[r][3] - m);
            float ssum = e0 + e1 + e2 + e3;
            ssum += __shfl_xor_sync(0x0000ffffu, ssum, 4);
            ssum += __shfl_xor_sync(0x0000ffffu, ssum, 8);
            float rinv = __frcp_rn(ssum);
            accr[r][0] = e0 * rinv; accr[r][1] = e1 * rinv;
            accr[r][2] = e2 * rinv; accr[r][3] = e3 * rinv;
        }
    }
    __syncthreads();   // qs reads complete everywhere -> safe to overlay

    if (sact) {
#pragma unroll
        for (int r = 0; r < 4; r++)
            *(float4*)&sc[pt][txi * 4 + r][tyi * 4] =
                make_float4(accr[r][0], accr[r][1], accr[r][2], accr[r][3]);
    }
    __syncthreads();

    // ---- AV: 320 units over 256 threads; unit = (pt, dg, xt), 4x4 tile ----
    for (int u = tid; u < 320; u += 256) {
        const int ptv = u >> 6;
        const int r6 = u & 63;
        const int dg = r6 >> 2;        // 0..15
        const int xt = r6 & 3;         // 0..3
        float4 a[4];
#pragma unroll
        for (int r = 0; r < 4; r++) a[r] = make_float4(0.f, 0.f, 0.f, 0.f);
#pragma unroll
        for (int yy = 0; yy < 16; yy++) {
            int vslot = (yy >> 2) * 12 + (yy & 3) + 2 * ptv;
            float4 vv = *(const float4*)&vs[vslot][dg * 4];
#pragma unroll
            for (int r = 0; r < 4; r++) {
                float p = sc[ptv][xt * 4 + r][yy];
                a[r].x += p * vv.x; a[r].y += p * vv.y;
                a[r].z += p * vv.z; a[r].w += p * vv.w;
            }
        }
        float* ob = g_oscr + ((size_t)((n * 4 + h) * 100 + s0 + ptv)) * 1024;
#pragma unroll
        for (int r = 0; r < 4; r++)
            *(float4*)&ob[(size_t)(xt * 4 + r) * 64 + dg * 4] = a[r];
    }
}

// ---------------------------------------------------------------------------
// Writeout: full output = bias everywhere, gathered proj value at active px
// ---------------------------------------------------------------------------
__global__ __launch_bounds__(256) void writeout(float* __restrict__ out,
                                                const float* __restrict__ b_proj) {
    size_t i4 = (size_t)blockIdx.x * 256 + threadIdx.x;
    if (i4 >= 8388608u) return;
    int ww0 = (int)(i4 & 15) * 4;
    int hh  = (int)(i4 >> 4) & 63;
    int c   = (int)(i4 >> 10) & 255;
    int n   = (int)(i4 >> 18);
    float bv = b_proj[c];
    float4 r = make_float4(bv, bv, bv, bv);
    if (hh % 3 == 0) {
        const float* pr = g_pout + ((size_t)(n * 256 + c)) * PACT + (hh / 3) * 22;
        if ((ww0 + 0) % 3 == 0) r.x = pr[(ww0 + 0) / 3];
        if ((ww0 + 1) % 3 == 0) r.y = pr[(ww0 + 1) / 3];
        if ((ww0 + 2) % 3 == 0) r.z = pr[(ww0 + 2) / 3];
        if ((ww0 + 3) % 3 == 0) r.w = pr[(ww0 + 3) / 3];
    }
    ((float4*)out)[i4] = r;
}

extern "C" void kernel_launch(void* const* d_in, const int* in_sizes, int n_in,
                              void* d_out, int out_size) {
    const float* q      = (const float*)d_in[0];
    const float* w_q    = (const float*)d_in[1];
    const float* b_q    = (const float*)d_in[2];
    const float* w_kv   = (const float*)d_in[3];
    const float* b_kv   = (const float*)d_in[4];
    const float* w_proj = (const float*)d_in[5];
    const float* b_proj = (const float*)d_in[6];
    float* out = (float*)d_out;

    prep_kernel<<<260, 256>>>(w_q, b_q, w_kv, b_kv, w_proj);
    pack_q<<<dim3(2, 32, NB), 256>>>(q);
    gemm_qkv_tc<<<dim3(4, 6, NB), 256>>>();
    attn_kernel<<<dim3(20, 4, NB), 256>>>();
    gemm_proj_tc<<<dim3(4, 2, NB), 256>>>(b_proj);
    writeout<<<32768, 256>>>(out, b_proj);
}

// round 13
// speedup vs baseline: 1.0786x; 1.0786x over previous
#include <cuda_runtime.h>
#include <cstdint>

#define PACT 484      // 22*22 active pixels
#define NB   32

// Scratch (static device allocations - allowed)
__device__ float    g_qkva [(size_t)NB * 768 * PACT];    // qp | k | v at active pixels
__device__ float    g_oscr [(size_t)NB * 4 * 100 * 1024];// o patches [n][h][s][l(16)][d(64)]
__device__ float    g_folded[(size_t)NB * 256 * PACT];   // folded at active pixels
__device__ float    g_pout [(size_t)NB * 256 * PACT];    // proj output at active pixels
__device__ unsigned g_wfrag1[48 * 32 * 128];             // [w_q;w_kv] tf32 A-fragments
__device__ unsigned g_wfrag2[16 * 32 * 128];             // w_proj tf32 A-fragments
__device__ unsigned g_qpack[(size_t)NB * 32 * 512 * 8];  // gathered q, tf32 B-fragment layout
__device__ float    g_bias768[768];

__device__ __forceinline__ unsigned f2tf(float f) {
    unsigned r; asm("cvt.rna.tf32.f32 %0, %1;" : "=r"(r) : "f"(f)); return r;
}

__device__ __forceinline__ void mma_tf32(float* d, const unsigned* a, unsigned b0, unsigned b1) {
    asm("mma.sync.aligned.m16n8k8.row.col.f32.tf32.tf32.f32 "
        "{%0,%1,%2,%3},{%4,%5,%6,%7},{%8,%9},{%0,%1,%2,%3};\n"
        : "+f"(d[0]), "+f"(d[1]), "+f"(d[2]), "+f"(d[3])
        : "r"(a[0]), "r"(a[1]), "r"(a[2]), "r"(a[3]), "r"(b0), "r"(b1));
}

__device__ __forceinline__ void cp_async16(void* smem_dst, const void* gmem_src) {
    unsigned dst = (unsigned)__cvta_generic_to_shared(smem_dst);
    asm volatile("cp.async.cg.shared.global [%0], [%1], 16;\n"
                 :: "r"(dst), "l"(gmem_src));
}
__device__ __forceinline__ void cp_commit() {
    asm volatile("cp.async.commit_group;\n");
}
__device__ __forceinline__ void cp_wait2() {
    asm volatile("cp.async.wait_group 2;\n");
}

// ---------------------------------------------------------------------------
// Pack + Prep fused: pack gathers q at active pixels -> tf32 B-fragment
// layout (all 2048 blocks); the first 260 blocks ALSO convert the weights
// into A-fragment layout and concat the biases (prep).
// ---------------------------------------------------------------------------
__global__ __launch_bounds__(256) void pack_prep(const float* __restrict__ q,
                                                 const float* __restrict__ w_q,
                                                 const float* __restrict__ b_q,
                                                 const float* __restrict__ w_kv,
                                                 const float* __restrict__ b_kv,
                                                 const float* __restrict__ w_proj) {
    // ---- prep part (first 260 blocks in flattened order) ----
    const int gbid = blockIdx.x + 2 * (blockIdx.y + 32 * blockIdx.z);
    if (gbid < 260) {
        int t = gbid * 256 + threadIdx.x;
        if (t < 49152) {                      // 48 mt * 32 ks * 32 lanes
            int lane = t & 31, ks = (t >> 5) & 31, mtg = t >> 10;
            int gid = lane >> 2, ctid = lane & 3;
            int r0 = mtg * 16 + gid, r1 = r0 + 8;
            int k0 = ks * 8 + ctid, k1 = k0 + 4;
            const float* W; int rb;
            if (r0 < 256) { W = w_q; rb = 0; } else { W = w_kv; rb = 256; }
            uint4 v = make_uint4(f2tf(W[(size_t)(r0 - rb) * 256 + k0]),
                                 f2tf(W[(size_t)(r1 - rb) * 256 + k0]),
                                 f2tf(W[(size_t)(r0 - rb) * 256 + k1]),
                                 f2tf(W[(size_t)(r1 - rb) * 256 + k1]));
            ((uint4*)g_wfrag1)[t] = v;
        } else if (t < 49152 + 16384) {       // 16 mt * 32 ks * 32 lanes
            int u = t - 49152;
            int lane = u & 31, ks = (u >> 5) & 31, mtg = u >> 10;
            int gid = lane >> 2, ctid = lane & 3;
            int r0 = mtg * 16 + gid, r1 = r0 + 8;
            int k0 = ks * 8 + ctid, k1 = k0 + 4;
            uint4 v = make_uint4(f2tf(w_proj[(size_t)r0 * 256 + k0]),
                                 f2tf(w_proj[(size_t)r1 * 256 + k0]),
                                 f2tf(w_proj[(size_t)r0 * 256 + k1]),
                                 f2tf(w_proj[(size_t)r1 * 256 + k1]));
            ((uint4*)g_wfrag2)[u] = v;
        } else if (t < 49152 + 16384 + 768) {
            int o = t - 49152 - 16384;
            g_bias768[o] = (o < 256) ? b_q[o] : b_kv[o - 256];
        }
    }

    // ---- pack part (all blocks) ----
    const int p  = blockIdx.x * 256 + threadIdx.x;   // 0..511
    const int kg = blockIdx.y;                       // 0..31
    const int n  = blockIdx.z;
    const float* qn = q + (size_t)n * 256 * 4096;
    unsigned o[8];
    if (p < PACT) {
        int m = p / 22, m2 = p - m * 22;
        size_t base = (size_t)(kg * 8) * 4096 + m * 192 + m2 * 3;
#pragma unroll
        for (int kk = 0; kk < 8; kk++)
            o[(kk & 3) * 2 + (kk >> 2)] = f2tf(qn[base + (size_t)kk * 4096]);
    } else {
#pragma unroll
        for (int i = 0; i < 8; i++) o[i] = 0u;
    }
    uint4* dst = (uint4*)(g_qpack + ((size_t)(n * 32 + kg) * 512 + p) * 8);
    dst[0] = make_uint4(o[0], o[1], o[2], o[3]);
    dst[1] = make_uint4(o[4], o[5], o[6], o[7]);
}

// ---------------------------------------------------------------------------
// TF32 GEMM1: per n, OUT(768,484) = [w_q;w_kv] @ gather(q) + bias
// B staged via 4-stage cp.async ring; A register-prefetched. float2 epilogue.
// ---------------------------------------------------------------------------
__global__ __launch_bounds__(256, 2) void gemm_qkv_tc() {
    __shared__ unsigned Bs[4][2][1024];   // 32 KB ring
    const int n = blockIdx.z, o0 = blockIdx.y * 128, p0 = blockIdx.x * 128;
    const int tid = threadIdx.x, lane = tid & 31, wid = tid >> 5;
    const int warp_m = wid >> 1, warp_n = wid & 1;
    const int gid = lane >> 2, ctid = lane & 3;

    float acc[2][8][4] = {};

    const uint4* src = (const uint4*)(g_qpack + ((size_t)(n * 32) * 512 + p0) * 8);
    auto issue_stage = [&](int s) {
#pragma unroll
        for (int ks = 0; ks < 2; ks++) {
            int kg = s * 2 + ks;
            cp_async16(&((uint4*)Bs[s & 3][ks])[tid], &src[(size_t)kg * 1024 + tid]);
        }
    };
    issue_stage(0); cp_commit();
    issue_stage(1); cp_commit();
    issue_stage(2); cp_commit();

    const int mtg0 = (o0 >> 4) + warp_m * 2;
    uint4 a_next[2];
#pragma unroll
    for (int mt = 0; mt < 2; mt++)
        a_next[mt] = ((const uint4*)g_wfrag1)[((mtg0 + mt) * 32 + 0) * 32 + lane];

    for (int iter = 0; iter < 16; iter++) {
        cp_wait2();
        __syncthreads();
        if (iter + 3 < 16) issue_stage(iter + 3);
        cp_commit();
        const int buf = iter & 3;
#pragma unroll
        for (int ks = 0; ks < 2; ks++) {
            int ksg = iter * 2 + ks;
            uint4 a_cur[2]; a_cur[0] = a_next[0]; a_cur[1] = a_next[1];
            if (ksg + 1 < 32) {
#pragma unroll
                for (int mt = 0; mt < 2; mt++)
                    a_next[mt] = ((const uint4*)g_wfrag1)[((mtg0 + mt) * 32 + ksg + 1) * 32 + lane];
            }
            unsigned a0[4] = {a_cur[0].x, a_cur[0].y, a_cur[0].z, a_cur[0].w};
            unsigned a1[4] = {a_cur[1].x, a_cur[1].y, a_cur[1].z, a_cur[1].w};
#pragma unroll
            for (int nt = 0; nt < 8; nt++) {
                const unsigned* bp = &Bs[buf][ks][warp_n * 512 + nt * 64 + lane * 2];
                unsigned b0 = bp[0], b1 = bp[1];
                mma_tf32(acc[0][nt], a0, b0, b1);
                mma_tf32(acc[1][nt], a1, b0, b1);
            }
        }
    }

    float* outb = g_qkva + (size_t)n * 768 * PACT;
#pragma unroll
    for (int mt = 0; mt < 2; mt++) {
        int row0 = o0 + warp_m * 32 + mt * 16 + gid;
#pragma unroll
        for (int half = 0; half < 2; half++) {
            int o = row0 + half * 8;
            float bv = g_bias768[o];
#pragma unroll
            for (int nt = 0; nt < 8; nt++) {
                int col = p0 + warp_n * 64 + nt * 8 + ctid * 2;   // always even
                if (col < PACT)
                    *(float2*)&outb[(size_t)o * PACT + col] =
                        make_float2(acc[mt][nt][half * 2 + 0] + bv,
                                    acc[mt][nt][half * 2 + 1] + bv);
            }
        }
    }
}

// ---------------------------------------------------------------------------
// TF32 GEMM2: per n, POUT(256,484) = w_proj @ folded + b_proj
// B staged via register software-pipeline. float2 epilogue.
// ---------------------------------------------------------------------------
__global__ __launch_bounds__(256, 2) void gemm_proj_tc(const float* __restrict__ b_proj) {
    __shared__ unsigned Bs[2][2][1024];
    const int n = blockIdx.z, o0 = blockIdx.y * 128, p0 = blockIdx.x * 128;
    const int tid = threadIdx.x, lane = tid & 31, wid = tid >> 5;
    const int warp_m = wid >> 1, warp_n = wid & 1;
    const int gid = lane >> 2, ctid = lane & 3;
    const float* Bn = g_folded + (size_t)n * 256 * PACT;

    float acc[2][8][4] = {};

    const int pl = tid & 127, kh = tid >> 7;
    const int pg = p0 + pl;
    float rvals[8];
    auto load_regs = [&](int iter) {
        int k0 = iter * 16 + kh * 8;
#pragma unroll
        for (int kk = 0; kk < 8; kk++)
            rvals[kk] = (pg < PACT) ? Bn[(size_t)(k0 + kk) * PACT + pg] : 0.f;
    };
    auto store_stage = [&](int iter) {
        int buf = iter & 1;
        unsigned o[8];
#pragma unroll
        for (int kk = 0; kk < 8; kk++)
            o[(kk & 3) * 2 + (kk >> 2)] = f2tf(rvals[kk]);
        uint4* dst = (uint4*)&Bs[buf][kh][pl * 8];
        dst[0] = make_uint4(o[0], o[1], o[2], o[3]);
        dst[1] = make_uint4(o[4], o[5], o[6], o[7]);
    };
    load_regs(0);
    store_stage(0);
    load_regs(1);
    __syncthreads();

    const int mtg0 = (o0 >> 4) + warp_m * 2;
    uint4 a_next[2];
#pragma unroll
    for (int mt = 0; mt < 2; mt++)
        a_next[mt] = ((const uint4*)g_wfrag2)[((mtg0 + mt) * 32 + 0) * 32 + lane];

    for (int iter = 0; iter < 16; iter++) {
        const int buf = iter & 1;
#pragma unroll
        for (int ks = 0; ks < 2; ks++) {
            int ksg = iter * 2 + ks;
            uint4 a_cur[2]; a_cur[0] = a_next[0]; a_cur[1] = a_next[1];
            if (ksg + 1 < 32) {
#pragma unroll
                for (int mt = 0; mt < 2; mt++)
                    a_next[mt] = ((const uint4*)g_wfrag2)[((mtg0 + mt) * 32 + ksg + 1) * 32 + lane];
            }
            unsigned a0[4] = {a_cur[0].x, a_cur[0].y, a_cur[0].z, a_cur[0].w};
            unsigned a1[4] = {a_cur[1].x, a_cur[1].y, a_cur[1].z, a_cur[1].w};
#pragma unroll
            for (int nt = 0; nt < 8; nt++) {
                const unsigned* bp = &Bs[buf][ks][warp_n * 512 + nt * 64 + lane * 2];
                unsigned b0 = bp[0], b1 = bp[1];
                mma_tf32(acc[0][nt], a0, b0, b1);
                mma_tf32(acc[1][nt], a1, b0, b1);
            }
        }
        if (iter + 1 < 16) store_stage(iter + 1);   // consumes rvals(iter+1)
        if (iter + 2 < 16) load_regs(iter + 2);     // refills rvals
        __syncthreads();
    }

    float* outb = g_pout + (size_t)n * 256 * PACT;
#pragma unroll
    for (int mt = 0; mt < 2; mt++) {
        int row0 = o0 + warp_m * 32 + mt * 16 + gid;
#pragma unroll
        for (int half = 0; half < 2; half++) {
            int o = row0 + half * 8;
            float bv = b_proj[o];
#pragma unroll
            for (int nt = 0; nt < 8; nt++) {
                int col = p0 + warp_n * 64 + nt * 8 + ctid * 2;   // always even
                if (col < PACT)
                    *(float2*)&outb[(size_t)o * PACT + col] =
                        make_float2(acc[mt][nt][half * 2 + 0] + bv,
                                    acc[mt][nt][half * 2 + 1] + bv);
            }
        }
    }
}

// ---------------------------------------------------------------------------
// Attention: block per (n, h, half-row). 5 patches s0..s0+4 in row i,
// i2 in [5*half, 5*half+5). Union: 4 image rows x 12 cols = 48 slots,
// slot = j*12 + jc, pixel poff = j*22 + jc. Tiles [slot][d(64)+4pad].
// Staging: 768 units (16 dg x 48 slots) over 256 threads, STS.128 each.
// Scores: warps 0-4 (one per patch), lanes 0..15, 4x4 (x,y) tile, kv[4]
//         held + qv streamed; row softmax via shfl_xor(4/8).
// AV: 320 units (pt, dg, xt) over 256 threads, 4x4 (x,d) tile each.
// o written [n][h][s][l][d] as float4.
// ---------------------------------------------------------------------------
__global__ __launch_bounds__(256, 5) void attn_kernel() {
    __shared__ float qs[48][68];
    __shared__ float ks[48][68];
    __shared__ float vs[48][68];
    __shared__ float sc[5][16][20];

    const int bx = blockIdx.x;         // 0..19
    const int i = bx >> 1;
    const int half = bx & 1;
    const int i2_0 = half * 5;
    const int s0 = i * 10 + i2_0;
    const int h = blockIdx.y;
    const int n = blockIdx.z;
    const int p0 = i * 44 + 2 * i2_0;

    const int tid = threadIdx.x;
    const int lane = tid & 31, wid = tid >> 5;
    const float* base = g_qkva + ((size_t)n * 768 + h * 64) * PACT + p0;

    // ---- staging: unit u = dg*48 + slot ----
    for (int u = tid; u < 768; u += 256) {
        const int dg = u / 48, slot = u - dg * 48;
        const int j = slot / 12, jc = slot - j * 12;
        const float* bq = base + (size_t)(dg * 4) * PACT + j * 22 + jc;
        const float* bk = bq + (size_t)256 * PACT;
        const float* bv = bq + (size_t)512 * PACT;
        float4 qv, kv, vv;
        qv.x = bq[0] * 0.125f;
        qv.y = bq[PACT] * 0.125f;
        qv.z = bq[2 * PACT] * 0.125f;
        qv.w = bq[3 * PACT] * 0.125f;
        kv.x = bk[0]; kv.y = bk[PACT]; kv.z = bk[2 * PACT]; kv.w = bk[3 * PACT];
        vv.x = bv[0]; vv.y = bv[PACT]; vv.z = bv[2 * PACT]; vv.w = bv[3 * PACT];
        *(float4*)&qs[slot][dg * 4] = qv;
        *(float4*)&ks[slot][dg * 4] = kv;
        *(float4*)&vs[slot][dg * 4] = vv;
    }
    __syncthreads();

    // ---- scores + softmax: warps 0..4 (patch = wid), lanes 0..15 ----
    if (wid < 5 && lane < 16) {
        const int pt = wid;
        const int txi = lane & 3;      // x-tile: x = txi*4 + r
        const int tyi = lane >> 2;     // y-tile: y = tyi*4 + c
        const int xs0 = txi * 12 + 2 * pt;   // xslot = xs0 + r
        const int ys0 = tyi * 12 + 2 * pt;   // yslot = ys0 + c

        float acc[4][4] = {};
#pragma unroll
        for (int dc = 0; dc < 16; dc++) {
            float4 kv[4];
#pragma unroll
            for (int c = 0; c < 4; c++) kv[c] = *(const float4*)&ks[ys0 + c][dc * 4];
#pragma unroll
            for (int r = 0; r < 4; r++) {
                float4 qv = *(const float4*)&qs[xs0 + r][dc * 4];
#pragma unroll
                for (int c = 0; c < 4; c++)
                    acc[r][c] += qv.x * kv[c].x + qv.y * kv[c].y
                               + qv.z * kv[c].z + qv.w * kv[c].w;
            }
        }
#pragma unroll
        for (int r = 0; r < 4; r++) {
            float m = fmaxf(fmaxf(acc[r][0], acc[r][1]), fmaxf(acc[r][2], acc[r][3]));
            m = fmaxf(m, __shfl_xor_sync(0x0000ffffu, m, 4));
            m = fmaxf(m, __shfl_xor_sync(0x0000ffffu, m, 8));
            float e0 = __expf(acc[r][0] - m), e1 = __expf(acc[r][1] - m);
            float e2 = __expf(acc[r][2] - m), e3 = __expf(acc[r][3] - m);
            float ssum = e0 + e1 + e2 + e3;
            ssum += __shfl_xor_sync(0x0000ffffu, ssum, 4);
            ssum += __shfl_xor_sync(0x0000ffffu, ssum, 8);
            float rinv = __frcp_rn(ssum);
            float4 pv = make_float4(e0 * rinv, e1 * rinv, e2 * rinv, e3 * rinv);
            *(float4*)&sc[pt][txi * 4 + r][tyi * 4] = pv;
        }
    }
    __syncthreads();

    // ---- AV: 320 units over 256 threads; unit = (pt, dg, xt), 4x4 tile ----
    for (int u = tid; u < 320; u += 256) {
        const int pt = u >> 6;
        const int r6 = u & 63;
        const int dg = r6 >> 2;        // 0..15
        const int xt = r6 & 3;         // 0..3
        float4 a[4];
#pragma unroll
        for (int r = 0; r < 4; r++) a[r] = make_float4(0.f, 0.f, 0.f, 0.f);
#pragma unroll
        for (int yy = 0; yy < 16; yy++) {
            int vslot = (yy >> 2) * 12 + (yy & 3) + 2 * pt;
            float4 vv = *(const float4*)&vs[vslot][dg * 4];
#pragma unroll
            for (int r = 0; r < 4; r++) {
                float p = sc[pt][xt * 4 + r][yy];
                a[r].x += p * vv.x; a[r].y += p * vv.y;
                a[r].z += p * vv.z; a[r].w += p * vv.w;
            }
        }
        float* ob = g_oscr + ((size_t)((n * 4 + h) * 100 + s0 + pt)) * 1024;
#pragma unroll
        for (int r = 0; r < 4; r++)
            *(float4*)&ob[(size_t)(xt * 4 + r) * 64 + dg * 4] = a[r];
    }
}

// ---------------------------------------------------------------------------
// Fold: block per (n, h, m-row). Reads contiguous [s][l-row][d] segments.
// ---------------------------------------------------------------------------
__global__ __launch_bounds__(256) void fold_kernel() {
    __shared__ float seg[2][10][256];
    const int bid = blockIdx.x;
    const int n = bid / 88;
    const int rem = bid - n * 88;
    const int h = rem / 22;
    const int m = rem - h * 22;

    int ia_min = (m - 3 + 1) >> 1; if (ia_min < 0) ia_min = 0;
    int ia_max = m >> 1;           if (ia_max > 9) ia_max = 9;
    const int nia = ia_max - ia_min + 1;   // 1 or 2

    const int tid = threadIdx.x;
    const float* obase = g_oscr + ((size_t)(n * 4 + h) * 100) * 1024;
    for (int f = tid; f < nia * 2560; f += 256) {
        int a = f / 2560, r = f - a * 2560;
        int ib = r >> 8, off = r & 255;
        int ia = ia_min + a;
        int ja = m - 2 * ia;
        seg[a][ib][off] = obase[(size_t)(ia * 10 + ib) * 1024 + ja * 256 + off];
    }
    __syncthreads();

    const int d = tid >> 2, sub = tid & 3;
    float* dst = g_folded + ((size_t)(n * 256 + h * 64 + d)) * PACT + m * 22;
    for (int m2 = sub; m2 < 22; m2 += 4) {
        float acc = 0.f;
        int jb0 = m2 & 1;
#pragma unroll
        for (int jj = 0; jj < 2; jj++) {
            int jb = jb0 + jj * 2;
            int ib = (m2 - jb) >> 1;
            if (ib < 0 || ib > 9) continue;
            acc += seg[0][ib][jb * 64 + d];
            if (nia == 2) acc += seg[1][ib][jb * 64 + d];
        }
        dst[m2] = acc;
    }
}

// ---------------------------------------------------------------------------
// Writeout: full output = bias everywhere, gathered proj value at active px
// ---------------------------------------------------------------------------
__global__ __launch_bounds__(256) void writeout(float* __restrict__ out,
                                                const float* __restrict__ b_proj) {
    size_t i4 = (size_t)blockIdx.x * 256 + threadIdx.x;
    if (i4 >= 8388608u) return;
    int ww0 = (int)(i4 & 15) * 4;
    int hh  = (int)(i4 >> 4) & 63;
    int c   = (int)(i4 >> 10) & 255;
    int n   = (int)(i4 >> 18);
    float bv = b_proj[c];
    float4 r = make_float4(bv, bv, bv, bv);
    if (hh % 3 == 0) {
        const float* pr = g_pout + ((size_t)(n * 256 + c)) * PACT + (hh / 3) * 22;
        if ((ww0 + 0) % 3 == 0) r.x = pr[(ww0 + 0) / 3];
        if ((ww0 + 1) % 3 == 0) r.y = pr[(ww0 + 1) / 3];
        if ((ww0 + 2) % 3 == 0) r.z = pr[(ww0 + 2) / 3];
        if ((ww0 + 3) % 3 == 0) r.w = pr[(ww0 + 3) / 3];
    }
    ((float4*)out)[i4] = r;
}

extern "C" void kernel_launch(void* const* d_in, const int* in_sizes, int n_in,
                              void* d_out, int out_size) {
    const float* q      = (const float*)d_in[0];
    const float* w_q    = (const float*)d_in[1];
    const float* b_q    = (const float*)d_in[2];
    const float* w_kv   = (const float*)d_in[3];
    const float* b_kv   = (const float*)d_in[4];
    const float* w_proj = (const float*)d_in[5];
    const float* b_proj = (const float*)d_in[6];
    float* out = (float*)d_out;

    pack_prep<<<dim3(2, 32, NB), 256>>>(q, w_q, b_q, w_kv, b_kv, w_proj);
    gemm_qkv_tc<<<dim3(4, 6, NB), 256>>>();
    attn_kernel<<<dim3(20, 4, NB), 256>>>();
    fold_kernel<<<dim3(NB * 4 * 22), 256>>>();
    gemm_proj_tc<<<dim3(4, 2, NB), 256>>>(b_proj);
    writeout<<<32768, 256>>>(out, b_proj);
}